// round 4
// baseline (speedup 1.0000x reference)
#include <cuda_runtime.h>

#define BB 16
#define TT 128
#define DD 1024
#define EE 128
#define HHN 128
#define GG 384           // 3*H
#define NSEQ (BB*TT)     // 2048
#define NGRP (NSEQ/4)    // 512

// scan smem layout (floats). B-role stores 24 weight pairs (h 80..127) at base.
#define SWP_PAIRS 24
#define OFF_SB   (SWP_PAIRS*384*2)      // 18432 floats of u64 weight pairs
#define OFF_SV   (OFF_SB + 384)
#define OFF_SH   (OFF_SV + 128)         // 4*132 floats, 16B aligned
#define OFF_AB   (OFF_SH + 4*132)
#define OFF_SIN  (OFF_AB + 4*384)
#define OFF_PART (OFF_SIN + 4*128)
#define OFF_SRED (OFF_PART + 4*384)
#define SMEM_FLOATS (OFF_SRED + 4*128)  // 23568 floats = 94272 B

// ---------------- scratch (device globals; no allocation) ----------------
__device__ float g_emb [NSEQ*EE];
__device__ float g_wemb[NSEQ*EE];
__device__ float g_GXa [NSEQ*GG];
__device__ float g_GXb [NSEQ*GG];
__device__ float g_pa  [NSEQ*TT];
__device__ float g_sv  [NSEQ*TT];

typedef unsigned long long ull;

__device__ __forceinline__ void ffma2(ull &d, ull a, ull b) {
    asm("fma.rn.f32x2 %0, %1, %2, %0;" : "+l"(d) : "l"(a), "l"(b));
}
__device__ __forceinline__ ull lds64v(unsigned a) {
    ull v; asm volatile("ld.shared.b64 %0, [%1];" : "=l"(v) : "r"(a)); return v;
}
__device__ __forceinline__ void lds128v(unsigned a, ull &p0, ull &p1) {
    asm volatile("ld.shared.v2.b64 {%0,%1}, [%2];" : "=l"(p0), "=l"(p1) : "r"(a));
}
__device__ __forceinline__ float pairsum(ull v) {
    return __uint_as_float((unsigned)v) + __uint_as_float((unsigned)(v >> 32));
}
__device__ __forceinline__ ull packf2(float lo, float hi) {
    return (ull)__float_as_uint(lo) | ((ull)__float_as_uint(hi) << 32);
}

// ---------------- Kernel 1: emb = x @ W_emb^T ; wemb = Wo .* emb ----------------
__global__ __launch_bounds__(256) void emb_kernel(
    const float* __restrict__ x, const float* __restrict__ Wemb,
    const float* __restrict__ Wo)
{
    __shared__ float sx[16][68];
    __shared__ float sw[16][36];
    int tid = threadIdx.x;
    int m0 = blockIdx.x * 64;
    int n0 = blockIdx.y * 32;
    int tx = tid & 15, ty = tid >> 4;
    int tm0 = tx * 4, tn0 = ty * 2;

    float acc[4][2];
#pragma unroll
    for (int q = 0; q < 4; q++) { acc[q][0] = 0.f; acc[q][1] = 0.f; }

    for (int kt = 0; kt < DD; kt += 16) {
        {
            int e = tid * 4; int m = e >> 4; int k = e & 15;
            float4 v = *(const float4*)(x + (size_t)(m0 + m) * DD + kt + k);
            sx[k][m] = v.x; sx[k+1][m] = v.y; sx[k+2][m] = v.z; sx[k+3][m] = v.w;
        }
        {
            int e = tid * 2; int n = e >> 4; int k = e & 15;
            float2 v = *(const float2*)(Wemb + (size_t)(n0 + n) * DD + kt + k);
            sw[k][n] = v.x; sw[k+1][n] = v.y;
        }
        __syncthreads();
#pragma unroll
        for (int k = 0; k < 16; k++) {
            float a0 = sx[k][tm0], a1 = sx[k][tm0+1], a2 = sx[k][tm0+2], a3 = sx[k][tm0+3];
            float b0 = sw[k][tn0], b1 = sw[k][tn0+1];
            acc[0][0] += a0*b0; acc[0][1] += a0*b1;
            acc[1][0] += a1*b0; acc[1][1] += a1*b1;
            acc[2][0] += a2*b0; acc[2][1] += a2*b1;
            acc[3][0] += a3*b0; acc[3][1] += a3*b1;
        }
        __syncthreads();
    }
#pragma unroll
    for (int q = 0; q < 4; q++)
#pragma unroll
        for (int r = 0; r < 2; r++) {
            int m = m0 + tm0 + q, n = n0 + tn0 + r;
            float v = acc[q][r];
            g_emb [m*EE + n] = v;
            g_wemb[m*EE + n] = v * Wo[n];
        }
}

// ---------------- Kernel 2: GX = emb @ Wih^T + bih (both GRUs) ----------------
__global__ __launch_bounds__(256) void gx_kernel(
    const float* __restrict__ Wih_a, const float* __restrict__ Wih_b,
    const float* __restrict__ bih_a, const float* __restrict__ bih_b)
{
    __shared__ float se [16][68];
    __shared__ float sw2[16][68];
    int tid = threadIdx.x;
    int m0 = blockIdx.x * 64;
    int n0 = blockIdx.y * 64;
    int tx = tid & 15, ty = tid >> 4;
    int tm0 = tx * 4, tn0 = ty * 4;

    const float* W; const float* bi; float* out; int nb;
    if (n0 < GG) { W = Wih_a; bi = bih_a; out = g_GXa; nb = n0; }
    else         { W = Wih_b; bi = bih_b; out = g_GXb; nb = n0 - GG; }

    float acc[4][4];
#pragma unroll
    for (int q = 0; q < 4; q++)
#pragma unroll
        for (int r = 0; r < 4; r++) acc[q][r] = 0.f;

    for (int kt = 0; kt < EE; kt += 16) {
        {
            int e = tid * 4; int m = e >> 4; int k = e & 15;
            float4 v = *(const float4*)(g_emb + (size_t)(m0 + m) * EE + kt + k);
            se[k][m] = v.x; se[k+1][m] = v.y; se[k+2][m] = v.z; se[k+3][m] = v.w;
        }
        {
            int e = tid * 4; int n = e >> 4; int k = e & 15;
            float4 v = *(const float4*)(W + (size_t)(nb + n) * EE + kt + k);
            sw2[k][n] = v.x; sw2[k+1][n] = v.y; sw2[k+2][n] = v.z; sw2[k+3][n] = v.w;
        }
        __syncthreads();
#pragma unroll
        for (int k = 0; k < 16; k++) {
            float a[4], b[4];
#pragma unroll
            for (int q = 0; q < 4; q++) a[q] = se[k][tm0+q];
#pragma unroll
            for (int r = 0; r < 4; r++) b[r] = sw2[k][tn0+r];
#pragma unroll
            for (int q = 0; q < 4; q++)
#pragma unroll
                for (int r = 0; r < 4; r++) acc[q][r] += a[q]*b[r];
        }
        __syncthreads();
    }
#pragma unroll
    for (int q = 0; q < 4; q++)
#pragma unroll
        for (int r = 0; r < 4; r++) {
            int m = m0 + tm0 + q, n = nb + tn0 + r;
            out[(size_t)m*GG + n] = acc[q][r] + bi[n];
        }
}

// ---------------- Kernel 3: persistent GRU scan (role-split A/B) ----------------
__global__ __launch_bounds__(384, 1) void scan_kernel(
    const float* __restrict__ Whh_a, const float* __restrict__ Whh_b,
    const float* __restrict__ bhh_a, const float* __restrict__ bhh_b,
    const float* __restrict__ Wa,    const float* __restrict__ ba,
    const float* __restrict__ Wb,    const float* __restrict__ bb,
    int RA, int Rtot)
{
    extern __shared__ float smem[];
    float* sB   = smem + OFF_SB;
    float* sV   = smem + OFF_SV;
    float* sh   = smem + OFF_SH;
    float* Ab   = smem + OFF_AB;
    float* sIn  = smem + OFF_SIN;
    float* part = smem + OFF_PART;
    float* sred = smem + OFF_SRED;

    unsigned sbase;
    asm("{ .reg .u64 t; cvta.to.shared.u64 t, %1; cvt.u32.u64 %0, t; }"
        : "=r"(sbase) : "l"(smem));
    unsigned shA  = sbase + OFF_SH * 4;
    unsigned sWpA = sbase;                 // u64 weight pairs (B role)

    int tid = threadIdx.x;
    int lane = tid & 31, warp = tid >> 5;
    bool roleA = (blockIdx.x < RA);
    int rc = roleA ? blockIdx.x : blockIdx.x - RA;
    int R  = roleA ? RA : (Rtot - RA);

    const float* Whh = roleA ? Whh_a : Whh_b;
    const float* bhh = roleA ? bhh_a : bhh_b;
    const float* GX  = roleA ? g_GXa : g_GXb;

    // weight registers: A uses w2[0..63] = Whh row pairs (h 0..127).
    // B uses w2[0..39] = Whh pairs (h 0..79), w2[40..61] = 0.5*Wb pairs for P3B.
    ull w2[64];
    int e3 = tid / 3, p3 = tid - e3*3, h0 = p3*44;
    {
        const ull* wp = (const ull*)(Whh + (size_t)tid * HHN);
        if (roleA) {
#pragma unroll
            for (int q = 0; q < 64; q++) w2[q] = wp[q];
        } else {
#pragma unroll
            for (int q = 0; q < 40; q++) w2[q] = wp[q];
            // stage remaining 24 pairs (h 80..127) to SMEM, column-major
            ull* swp = (ull*)smem;
#pragma unroll
            for (int i = 0; i < SWP_PAIRS; i++)
                swp[i*384 + tid] = wp[40 + i];
            // Wb pairs (scaled 0.5), padded with zeros past h=127
#pragma unroll
            for (int q = 0; q < 22; q++) {
                int h = h0 + 2*q;
                float x0 = (h   < HHN) ? 0.5f * Wb[e3*HHN + h]   : 0.f;
                float x1 = (h+1 < HHN) ? 0.5f * Wb[e3*HHN + h+1] : 0.f;
                w2[40 + q] = packf2(x0, x1);
            }
        }
    }
    sB[tid] = bhh[tid];
    if (tid < 128) sV[tid] = roleA ? (0.5f * Wa[tid]) : bb[tid];
    float rba = roleA ? ba[0] : 0.f;
    __syncthreads();

    for (int mIdx = 0;; mIdx++) {
        int gsel = mIdx*R + ((mIdx & 1) ? (R - 1 - rc) : rc);   // snake
        if (gsel >= NGRP) break;

        int iS[4], bS[4];
#pragma unroll
        for (int s = 0; s < 4; s++) {
            int n = gsel*4 + s;
            iS[s] = 127 - (n >> 4);    // longest-first
            bS[s] = n & 15;
        }
        int kmax = iS[0];

        __syncthreads();
        for (int idx = tid; idx < 4*132; idx += 384) sh[idx] = 0.f;
        __syncthreads();

        for (int k = 0; k <= kmax; k++) {
            bool act[4]; int jS[4]; float gi[4];
#pragma unroll
            for (int s = 0; s < 4; s++) {
                act[s] = (k <= iS[s]);
                jS[s] = act[s] ? (iS[s] - k) : 0;
            }
#pragma unroll
            for (int s = 0; s < 4; s++)
                gi[s] = GX[(size_t)(bS[s]*TT + jS[s])*GG + tid];

            float wem0 = 0.f, wem1 = 0.f;
            if (!roleA) {
                { int s = tid >> 7, e = tid & 127;
                  wem0 = g_wemb[(bS[s]*TT + jS[s])*EE + e]; }
                if (tid < 128)
                  wem1 = g_wemb[(bS[3]*TT + jS[3])*EE + tid];
            }

            // ---- P1: gh[g] = Whh[g,:]·h for 4 seqs (FFMA2, reg weights) ----
            ull ac0 = 0, ac1 = 0, ac2 = 0, ac3 = 0;
            if (roleA) {
#pragma unroll
                for (int i = 0; i < 32; i++) {
                    ull p0, p1;
                    lds128v(shA +          i*16, p0, p1);
                    ffma2(ac0, w2[2*i], p0); ffma2(ac0, w2[2*i+1], p1);
                    lds128v(shA +  528 +   i*16, p0, p1);
                    ffma2(ac1, w2[2*i], p0); ffma2(ac1, w2[2*i+1], p1);
                    lds128v(shA + 1056 +   i*16, p0, p1);
                    ffma2(ac2, w2[2*i], p0); ffma2(ac2, w2[2*i+1], p1);
                    lds128v(shA + 1584 +   i*16, p0, p1);
                    ffma2(ac3, w2[2*i], p0); ffma2(ac3, w2[2*i+1], p1);
                }
            } else {
#pragma unroll
                for (int i = 0; i < 20; i++) {
                    ull p0, p1;
                    lds128v(shA +          i*16, p0, p1);
                    ffma2(ac0, w2[2*i], p0); ffma2(ac0, w2[2*i+1], p1);
                    lds128v(shA +  528 +   i*16, p0, p1);
                    ffma2(ac1, w2[2*i], p0); ffma2(ac1, w2[2*i+1], p1);
                    lds128v(shA + 1056 +   i*16, p0, p1);
                    ffma2(ac2, w2[2*i], p0); ffma2(ac2, w2[2*i+1], p1);
                    lds128v(shA + 1584 +   i*16, p0, p1);
                    ffma2(ac3, w2[2*i], p0); ffma2(ac3, w2[2*i+1], p1);
                }
                // SMEM pairs h 80..127 (24 pairs, 2 per iter)
#pragma unroll
                for (int i = 0; i < 12; i++) {
                    ull wA = lds64v(sWpA + (unsigned)((2*i  )*384 + tid)*8);
                    ull wB = lds64v(sWpA + (unsigned)((2*i+1)*384 + tid)*8);
                    ull p0, p1;
                    lds128v(shA +          (320 + i*16), p0, p1);
                    ffma2(ac0, wA, p0); ffma2(ac0, wB, p1);
                    lds128v(shA +  528 +   (320 + i*16), p0, p1);
                    ffma2(ac1, wA, p0); ffma2(ac1, wB, p1);
                    lds128v(shA + 1056 +   (320 + i*16), p0, p1);
                    ffma2(ac2, wA, p0); ffma2(ac2, wB, p1);
                    lds128v(shA + 1584 +   (320 + i*16), p0, p1);
                    ffma2(ac3, wA, p0); ffma2(ac3, wB, p1);
                }
            }
            float a0 = pairsum(ac0), a1 = pairsum(ac1);
            float a2 = pairsum(ac2), a3 = pairsum(ac3);
            {
                float bt = sB[tid];
                if (tid < 256) {   // r,z gates
                    Ab[       tid] = a0 + gi[0] + bt;
                    Ab[ 384 + tid] = a1 + gi[1] + bt;
                    Ab[ 768 + tid] = a2 + gi[2] + bt;
                    Ab[1152 + tid] = a3 + gi[3] + bt;
                } else {           // n gate
                    int hp = tid - 256;
                    Ab[       tid] = a0 + bt;
                    Ab[ 384 + tid] = a1 + bt;
                    Ab[ 768 + tid] = a2 + bt;
                    Ab[1152 + tid] = a3 + bt;
                    sIn[      hp] = gi[0];
                    sIn[128 + hp] = gi[1];
                    sIn[256 + hp] = gi[2];
                    sIn[384 + hp] = gi[3];
                }
            }
            __syncthreads();

            // ---- P2: GRU state update (512 units) ----
            {
                int s = tid >> 7, hp = tid & 127;
                float ar = Ab[s*384 + hp];
                float az = Ab[s*384 + 128 + hp];
                float hn = Ab[s*384 + 256 + hp];
                float xi = sIn[s*128 + hp];
                float r = __fdividef(1.f, 1.f + __expf(-ar));
                float z = __fdividef(1.f, 1.f + __expf(-az));
                float nn = tanhf(xi + r*hn);
                float ho = sh[s*132 + hp];
                sh[s*132 + hp] = (1.f - z)*nn + z*ho;
            }
            if (tid < 128) {
                int s = 3, hp = tid;
                float ar = Ab[s*384 + hp];
                float az = Ab[s*384 + 128 + hp];
                float hn = Ab[s*384 + 256 + hp];
                float xi = sIn[s*128 + hp];
                float r = __fdividef(1.f, 1.f + __expf(-ar));
                float z = __fdividef(1.f, 1.f + __expf(-az));
                float nn = tanhf(xi + r*hn);
                float ho = sh[s*132 + hp];
                sh[s*132 + hp] = (1.f - z)*nn + z*ho;
            }
            __syncthreads();

            if (roleA) {
                // ---- P3A: pre_alpha = 0.5*Wa·h + ba ----
                if (warp < 4) {
                    int s = warp;
                    const float* hs = sh + s*132;
                    float p = sV[lane]      * hs[lane]
                            + sV[32 + lane] * hs[32 + lane]
                            + sV[64 + lane] * hs[64 + lane]
                            + sV[96 + lane] * hs[96 + lane];
#pragma unroll
                    for (int o = 16; o > 0; o >>= 1)
                        p += __shfl_xor_sync(0xffffffffu, p, o);
                    if (lane == 0 && act[s])
                        g_pa[(size_t)(bS[s]*TT + iS[s])*TT + k] = p + rba;
                }
            } else {
                // ---- P3B: part = 0.5*Wb·h (FFMA2, reg pairs, 3 thirds/e) ----
                {
                    ull pp0 = 0, pp1 = 0, pp2 = 0, pp3 = 0;
                    unsigned hb = shA + (unsigned)h0*4;
#pragma unroll
                    for (int q = 0; q < 22; q++) {
                        ull w = w2[40 + q];
                        ffma2(pp0, w, lds64v(hb +          q*8));
                        ffma2(pp1, w, lds64v(hb +  528 +   q*8));
                        ffma2(pp2, w, lds64v(hb + 1056 +   q*8));
                        ffma2(pp3, w, lds64v(hb + 1584 +   q*8));
                    }
                    part[       tid] = pairsum(pp0);
                    part[ 384 + tid] = pairsum(pp1);
                    part[ 768 + tid] = pairsum(pp2);
                    part[1152 + tid] = pairsum(pp3);
                }
                __syncthreads();
                // ---- P4: beta = tanh(.+bb); contrib = beta*wemb ----
                {
                    int s = tid >> 7, e = tid & 127;
                    float m3 = part[s*384 + e*3] + part[s*384 + e*3 + 1]
                             + part[s*384 + e*3 + 2] + sV[e];
                    sred[tid] = tanhf(m3) * wem0;
                }
                if (tid < 128) {
                    int s = 3, e = tid;
                    float m3 = part[s*384 + e*3] + part[s*384 + e*3 + 1]
                             + part[s*384 + e*3 + 2] + sV[e];
                    sred[384 + tid] = tanhf(m3) * wem1;
                }
                __syncthreads();
                // ---- P5: s[k] = sum_e contrib ----
                if (warp < 4) {
                    int s = warp;
                    float v = sred[s*128 + lane]      + sred[s*128 + 32 + lane]
                            + sred[s*128 + 64 + lane] + sred[s*128 + 96 + lane];
#pragma unroll
                    for (int o = 16; o > 0; o >>= 1)
                        v += __shfl_xor_sync(0xffffffffu, v, o);
                    if (lane == 0 && act[s])
                        g_sv[(size_t)(bS[s]*TT + iS[s])*TT + k] = v;
                }
            }
        } // k
    } // groups
}

// ---------------- Kernel 4: masked softmax combine ----------------
__global__ __launch_bounds__(256) void combine_kernel(
    const float* __restrict__ bo, float* __restrict__ out)
{
    int w = blockIdx.x * 8 + (threadIdx.x >> 5);
    int lane = threadIdx.x & 31;
    if (w >= NSEQ) return;
    int i = w & 127;
    float num = 0.f, den = 0.f;
    for (int k = lane; k <= i; k += 32) {
        float ev = __expf(g_pa[(size_t)w*TT + k]);
        num += ev * g_sv[(size_t)w*TT + k];
        den += ev;
    }
#pragma unroll
    for (int o = 16; o > 0; o >>= 1) {
        num += __shfl_xor_sync(0xffffffffu, num, o);
        den += __shfl_xor_sync(0xffffffffu, den, o);
    }
    if (lane == 0) out[w] = num / den + bo[0];
}

// ---------------- launch ----------------
extern "C" void kernel_launch(void* const* d_in, const int* in_sizes, int n_in,
                              void* d_out, int out_size)
{
    const float* x     = (const float*)d_in[0];
    const float* Wemb  = (const float*)d_in[1];
    const float* Wih_a = (const float*)d_in[2];
    const float* Whh_a = (const float*)d_in[3];
    const float* bih_a = (const float*)d_in[4];
    const float* bhh_a = (const float*)d_in[5];
    const float* Wa    = (const float*)d_in[6];
    const float* ba    = (const float*)d_in[7];
    const float* Wih_b = (const float*)d_in[8];
    const float* Whh_b = (const float*)d_in[9];
    const float* bih_b = (const float*)d_in[10];
    const float* bhh_b = (const float*)d_in[11];
    const float* Wb    = (const float*)d_in[12];
    const float* bb    = (const float*)d_in[13];
    const float* Wo    = (const float*)d_in[14];
    const float* bo    = (const float*)d_in[15];
    float* out = (float*)d_out;

    int dev = 0;
    cudaGetDevice(&dev);
    int sms = 148;
    cudaDeviceGetAttribute(&sms, cudaDevAttrMultiProcessorCount, dev);
    int RA = (int)(sms * 0.435f + 0.5f);
    if (RA < 1) RA = 1;
    if (RA > sms - 1) RA = sms - 1;

    size_t smem_bytes = (size_t)SMEM_FLOATS * sizeof(float);
    cudaFuncSetAttribute(scan_kernel,
                         cudaFuncAttributeMaxDynamicSharedMemorySize,
                         (int)smem_bytes);

    emb_kernel<<<dim3(32, 4), 256>>>(x, Wemb, Wo);
    gx_kernel<<<dim3(32, 12), 256>>>(Wih_a, Wih_b, bih_a, bih_b);
    scan_kernel<<<sms, 384, smem_bytes>>>(Whh_a, Whh_b, bhh_a, bhh_b,
                                          Wa, ba, Wb, bb, RA, sms);
    combine_kernel<<<NSEQ/8, 256>>>(bo, out);
}

// round 5
// speedup vs baseline: 1.3557x; 1.3557x over previous
#include <cuda_runtime.h>

#define BB 16
#define TT 128
#define DD 1024
#define EE 128
#define HHN 128
#define GG 384           // 3*H
#define NSEQ (BB*TT)     // 2048
#define NG8  256         // groups of 8 seqs (2 per time position i)

// scan smem layout (floats)
#define OFF_SB   12288                  // after 16*384 ull weight pairs
#define OFF_SH   (OFF_SB + 384)         // 8*132 hidden states (16B aligned)
#define OFF_AB   (OFF_SH + 8*132)       // 8*384 gate pre-activations
#define OFF_SIN  (OFF_AB + 8*384)       // 8*128 n-gate inputs
#define SMEM_FLOATS (OFF_SIN + 8*128)   // 17824 floats = 71296 B

// ---------------- scratch (device globals; no allocation) ----------------
__device__ float g_emb [NSEQ*EE];
__device__ float g_wemb[NSEQ*EE];       // Wo[e]*emb
__device__ float g_GXa [NSEQ*GG];
__device__ float g_GXb [NSEQ*GG];
__device__ float g_pa  [NSEQ*TT];       // pre_alpha[n][k]
__device__ float g_sv  [NSEQ*TT];       // s[n][k]
__device__ float g_hsa [(size_t)TT*NSEQ*HHN];   // h_a[k][n][h]  134MB
__device__ float g_hsb [(size_t)TT*NSEQ*HHN];   // h_b[k][n][h]  134MB
__device__ int   g_dummy;

typedef unsigned long long ull;

__device__ __forceinline__ void ffma2(ull &d, ull a, ull b) {
    asm("fma.rn.f32x2 %0, %1, %2, %0;" : "+l"(d) : "l"(a), "l"(b));
}
__device__ __forceinline__ ull lds64v(unsigned a) {
    ull v; asm volatile("ld.shared.b64 %0, [%1];" : "=l"(v) : "r"(a)); return v;
}
__device__ __forceinline__ void lds128v(unsigned a, ull &p0, ull &p1) {
    asm volatile("ld.shared.v2.b64 {%0,%1}, [%2];" : "=l"(p0), "=l"(p1) : "r"(a));
}
__device__ __forceinline__ float pairsum(ull v) {
    return __uint_as_float((unsigned)v) + __uint_as_float((unsigned)(v >> 32));
}

// ---------------- dummy (shifts ncu capture slot onto the scan) ----------------
__global__ void dummy_kernel() { if (threadIdx.x == 0) g_dummy = 1; }

// ---------------- Kernel 1: emb = x @ W_emb^T ; wemb = Wo .* emb ----------------
__global__ __launch_bounds__(256) void emb_kernel(
    const float* __restrict__ x, const float* __restrict__ Wemb,
    const float* __restrict__ Wo)
{
    __shared__ float sx[16][68];
    __shared__ float sw[16][36];
    int tid = threadIdx.x;
    int m0 = blockIdx.x * 64;
    int n0 = blockIdx.y * 32;
    int tx = tid & 15, ty = tid >> 4;
    int tm0 = tx * 4, tn0 = ty * 2;

    float acc[4][2];
#pragma unroll
    for (int q = 0; q < 4; q++) { acc[q][0] = 0.f; acc[q][1] = 0.f; }

    for (int kt = 0; kt < DD; kt += 16) {
        {
            int e = tid * 4; int m = e >> 4; int k = e & 15;
            float4 v = *(const float4*)(x + (size_t)(m0 + m) * DD + kt + k);
            sx[k][m] = v.x; sx[k+1][m] = v.y; sx[k+2][m] = v.z; sx[k+3][m] = v.w;
        }
        {
            int e = tid * 2; int n = e >> 4; int k = e & 15;
            float2 v = *(const float2*)(Wemb + (size_t)(n0 + n) * DD + kt + k);
            sw[k][n] = v.x; sw[k+1][n] = v.y;
        }
        __syncthreads();
#pragma unroll
        for (int k = 0; k < 16; k++) {
            float a0 = sx[k][tm0], a1 = sx[k][tm0+1], a2 = sx[k][tm0+2], a3 = sx[k][tm0+3];
            float b0 = sw[k][tn0], b1 = sw[k][tn0+1];
            acc[0][0] += a0*b0; acc[0][1] += a0*b1;
            acc[1][0] += a1*b0; acc[1][1] += a1*b1;
            acc[2][0] += a2*b0; acc[2][1] += a2*b1;
            acc[3][0] += a3*b0; acc[3][1] += a3*b1;
        }
        __syncthreads();
    }
#pragma unroll
    for (int q = 0; q < 4; q++)
#pragma unroll
        for (int r = 0; r < 2; r++) {
            int m = m0 + tm0 + q, n = n0 + tn0 + r;
            float v = acc[q][r];
            g_emb [m*EE + n] = v;
            g_wemb[m*EE + n] = v * Wo[n];
        }
}

// ---------------- Kernel 2: GX = emb @ Wih^T + bih (both GRUs) ----------------
__global__ __launch_bounds__(256) void gx_kernel(
    const float* __restrict__ Wih_a, const float* __restrict__ Wih_b,
    const float* __restrict__ bih_a, const float* __restrict__ bih_b)
{
    __shared__ float se [16][68];
    __shared__ float sw2[16][68];
    int tid = threadIdx.x;
    int m0 = blockIdx.x * 64;
    int n0 = blockIdx.y * 64;
    int tx = tid & 15, ty = tid >> 4;
    int tm0 = tx * 4, tn0 = ty * 4;

    const float* W; const float* bi; float* out; int nb;
    if (n0 < GG) { W = Wih_a; bi = bih_a; out = g_GXa; nb = n0; }
    else         { W = Wih_b; bi = bih_b; out = g_GXb; nb = n0 - GG; }

    float acc[4][4];
#pragma unroll
    for (int q = 0; q < 4; q++)
#pragma unroll
        for (int r = 0; r < 4; r++) acc[q][r] = 0.f;

    for (int kt = 0; kt < EE; kt += 16) {
        {
            int e = tid * 4; int m = e >> 4; int k = e & 15;
            float4 v = *(const float4*)(g_emb + (size_t)(m0 + m) * EE + kt + k);
            se[k][m] = v.x; se[k+1][m] = v.y; se[k+2][m] = v.z; se[k+3][m] = v.w;
        }
        {
            int e = tid * 4; int n = e >> 4; int k = e & 15;
            float4 v = *(const float4*)(W + (size_t)(nb + n) * EE + kt + k);
            sw2[k][n] = v.x; sw2[k+1][n] = v.y; sw2[k+2][n] = v.z; sw2[k+3][n] = v.w;
        }
        __syncthreads();
#pragma unroll
        for (int k = 0; k < 16; k++) {
            float a[4], b[4];
#pragma unroll
            for (int q = 0; q < 4; q++) a[q] = se[k][tm0+q];
#pragma unroll
            for (int r = 0; r < 4; r++) b[r] = sw2[k][tn0+r];
#pragma unroll
            for (int q = 0; q < 4; q++)
#pragma unroll
                for (int r = 0; r < 4; r++) acc[q][r] += a[q]*b[r];
        }
        __syncthreads();
    }
#pragma unroll
    for (int q = 0; q < 4; q++)
#pragma unroll
        for (int r = 0; r < 4; r++) {
            int m = m0 + tm0 + q, n = nb + tn0 + r;
            out[(size_t)m*GG + n] = acc[q][r] + bi[n];
        }
}

// ---------------- Kernel 3: persistent GRU scan (pure recurrence) ----------------
// 8 same-length seqs per group; A and B roles identical in cost; h stored to global.
__global__ __launch_bounds__(384, 1) void scan_kernel(
    const float* __restrict__ Whh_a, const float* __restrict__ Whh_b,
    const float* __restrict__ bhh_a, const float* __restrict__ bhh_b,
    int RA, int Rtot)
{
    extern __shared__ float smem[];
    float* sB  = smem + OFF_SB;
    float* sh  = smem + OFF_SH;
    float* Ab  = smem + OFF_AB;
    float* sIn = smem + OFF_SIN;

    unsigned sbase;
    asm("{ .reg .u64 t; cvta.to.shared.u64 t, %1; cvt.u32.u64 %0, t; }"
        : "=r"(sbase) : "l"(smem));
    unsigned sWp = sbase;                 // 16*384 ull weight pairs (h 96..127)
    unsigned shA = sbase + OFF_SH * 4;    // hidden states, 528B per seq

    int tid = threadIdx.x;
    bool roleA = (blockIdx.x < RA);
    int rc = roleA ? blockIdx.x : blockIdx.x - RA;
    int R  = roleA ? RA : (Rtot - RA);

    const float* Whh = roleA ? Whh_a : Whh_b;
    const float* bhh = roleA ? bhh_a : bhh_b;
    const float* GX  = roleA ? g_GXa : g_GXb;
    float* HS        = roleA ? g_hsa : g_hsb;

    // weights: gate row tid; h 0..95 in regs (48 ull), h 96..127 in SMEM
    ull w2[48];
    {
        const ull* wp = (const ull*)(Whh + (size_t)tid * HHN);
#pragma unroll
        for (int q = 0; q < 48; q++) w2[q] = wp[q];
        ull* swp = (ull*)smem;
#pragma unroll
        for (int p = 0; p < 16; p++) swp[p*384 + tid] = wp[48 + p];
    }
    sB[tid] = bhh[tid];
    __syncthreads();

    for (int mIdx = 0;; mIdx++) {
        int g = mIdx*R + ((mIdx & 1) ? (R - 1 - rc) : rc);   // snake
        if (g >= NG8) break;

        int i  = 127 - (g >> 1);      // longest-first
        int b0 = (g & 1) * 8;
        int base_s[8];
#pragma unroll
        for (int s = 0; s < 8; s++)
            base_s[s] = ((b0 + s)*TT + i)*GG + tid;

        __syncthreads();
        for (int idx = tid; idx < 8*132; idx += 384) sh[idx] = 0.f;
        __syncthreads();

        for (int k = 0; k <= i; k++) {
            // prefetch input-side gates (L2-resident)
            float gi[8];
            int koff = k * GG;
#pragma unroll
            for (int s = 0; s < 8; s++)
                gi[s] = __ldg(GX + base_s[s] - koff);

            // ---- P1: gh = Whh[tid,:]·h for 8 seqs (f32x2 over h) ----
            ull acc[8];
#pragma unroll
            for (int s = 0; s < 8; s++) acc[s] = 0;
#pragma unroll
            for (int blk = 0; blk < 24; blk++) {
                ull w0 = w2[2*blk], w1 = w2[2*blk+1];
#pragma unroll
                for (int s = 0; s < 8; s++) {
                    ull p0, p1;
                    lds128v(shA + (unsigned)(s*528 + blk*16), p0, p1);
                    ffma2(acc[s], w0, p0); ffma2(acc[s], w1, p1);
                }
            }
#pragma unroll
            for (int blk = 0; blk < 8; blk++) {
                ull w0 = lds64v(sWp + (unsigned)((2*blk  )*384 + tid)*8);
                ull w1 = lds64v(sWp + (unsigned)((2*blk+1)*384 + tid)*8);
#pragma unroll
                for (int s = 0; s < 8; s++) {
                    ull p0, p1;
                    lds128v(shA + (unsigned)(s*528 + 384 + blk*16), p0, p1);
                    ffma2(acc[s], w0, p0); ffma2(acc[s], w1, p1);
                }
            }
            {
                float bt = sB[tid];
                if (tid < 256) {            // r,z gates: full pre-activation
#pragma unroll
                    for (int s = 0; s < 8; s++)
                        Ab[s*384 + tid] = pairsum(acc[s]) + gi[s] + bt;
                } else {                    // n gate: keep h-part and i-part split
                    int hp = tid - 256;
#pragma unroll
                    for (int s = 0; s < 8; s++) {
                        Ab[s*384 + tid] = pairsum(acc[s]) + bt;
                        sIn[s*128 + hp] = gi[s];
                    }
                }
            }
            __syncthreads();

            // ---- P2: GRU update, 1024 units; write sh + global h ----
#pragma unroll
            for (int pass = 0; pass < 3; pass++) {
                int u = tid + pass*384;
                if (u < 1024) {
                    int s = u >> 7, hp = u & 127;
                    float ar = Ab[s*384 + hp];
                    float az = Ab[s*384 + 128 + hp];
                    float hn = Ab[s*384 + 256 + hp];
                    float xi = sIn[s*128 + hp];
                    float r = __fdividef(1.f, 1.f + __expf(-ar));
                    float z = __fdividef(1.f, 1.f + __expf(-az));
                    float nn = tanhf(xi + r*hn);
                    float ho = sh[s*132 + hp];
                    float h2 = (1.f - z)*nn + z*ho;
                    sh[s*132 + hp] = h2;
                    int n = (b0 + s)*TT + i;
                    HS[((size_t)k*NSEQ + n)*HHN + hp] = h2;
                }
            }
            __syncthreads();
        } // k
    } // groups
}

// ---------------- Kernel 4: pre_alpha = 0.5*Wa·h_a + ba ----------------
__global__ __launch_bounds__(256) void alpha_kernel(
    const float* __restrict__ Wa, const float* __restrict__ ba)
{
    int r = blockIdx.x * 8 + (threadIdx.x >> 5);   // (k,n) flat
    int lane = threadIdx.x & 31;
    int k = r >> 11, n = r & 2047, i = n & 127;
    if (k > i) return;
    const float4 hv = *(const float4*)(g_hsa + ((size_t)k*NSEQ + n)*HHN + lane*4);
    const float4 wv = *(const float4*)(Wa + lane*4);
    float p = 0.5f*(hv.x*wv.x + hv.y*wv.y + hv.z*wv.z + hv.w*wv.w);
#pragma unroll
    for (int o = 16; o > 0; o >>= 1)
        p += __shfl_xor_sync(0xffffffffu, p, o);
    if (lane == 0) g_pa[(size_t)n*TT + k] = p + ba[0];
}

// ---------------- Kernel 5: beta GEMM + wemb dot -> s[n][k] ----------------
// CTA: fixed k, 64 consecutive n (same b). C = (0.5*h_b)@Wb^T + bb; tanh; dot wemb.
__global__ __launch_bounds__(256) void beta_kernel(
    const float* __restrict__ Wb, const float* __restrict__ bb)
{
    int k  = blockIdx.x;          // 0..127
    int nb = blockIdx.y;          // 0..31
    int i0 = (nb & 1) * 64;
    if (i0 + 63 < k) return;      // whole block invalid
    int n0 = nb * 64;
    int b  = n0 >> 7;

    __shared__ float shh[16][68];
    __shared__ float sww[16][132];
    __shared__ float red[64][17];

    int tid = threadIdx.x;
    int tx = tid & 15, ty = tid >> 4;    // tx: 16 row-groups(4), ty: 16 e-groups(8)
    int r0 = tx * 4, e0 = ty * 8;

    const float* hb = g_hsb + ((size_t)k*NSEQ + n0)*HHN;

    float acc[4][8];
#pragma unroll
    for (int q = 0; q < 4; q++)
#pragma unroll
        for (int e = 0; e < 8; e++) acc[q][e] = 0.f;

    for (int kt = 0; kt < HHN; kt += 16) {
        {
            int e = tid * 4; int rr = e >> 4; int h = e & 15;
            float4 v = *(const float4*)(hb + (size_t)rr*HHN + kt + h);
            shh[h][rr] = v.x; shh[h+1][rr] = v.y; shh[h+2][rr] = v.z; shh[h+3][rr] = v.w;
        }
        {
            int e2 = tid * 8; int ee = e2 >> 4; int h = e2 & 15;
            float4 v0 = *(const float4*)(Wb + (size_t)ee*HHN + kt + h);
            float4 v1 = *(const float4*)(Wb + (size_t)ee*HHN + kt + h + 4);
            sww[h  ][ee] = 0.5f*v0.x; sww[h+1][ee] = 0.5f*v0.y;
            sww[h+2][ee] = 0.5f*v0.z; sww[h+3][ee] = 0.5f*v0.w;
            sww[h+4][ee] = 0.5f*v1.x; sww[h+5][ee] = 0.5f*v1.y;
            sww[h+6][ee] = 0.5f*v1.z; sww[h+7][ee] = 0.5f*v1.w;
        }
        __syncthreads();
#pragma unroll
        for (int kk = 0; kk < 16; kk++) {
            float a[4], bv[8];
#pragma unroll
            for (int q = 0; q < 4; q++) a[q] = shh[kk][r0+q];
#pragma unroll
            for (int e = 0; e < 8; e++) bv[e] = sww[kk][e0+e];
#pragma unroll
            for (int q = 0; q < 4; q++)
#pragma unroll
                for (int e = 0; e < 8; e++) acc[q][e] += a[q]*bv[e];
        }
        __syncthreads();
    }

    float bbv[8];
#pragma unroll
    for (int e = 0; e < 8; e++) bbv[e] = bb[e0 + e];

#pragma unroll
    for (int q = 0; q < 4; q++) {
        int n = n0 + r0 + q;
        int i = n & 127;
        int j = i - k;
        const float* wm = g_wemb + ((size_t)b*TT + (j >= 0 ? j : 0))*EE + e0;
        float p = 0.f;
#pragma unroll
        for (int e = 0; e < 8; e++)
            p += tanhf(acc[q][e] + bbv[e]) * wm[e];
        red[r0 + q][ty] = p;
    }
    __syncthreads();
    if (tid < 64) {
        float v = 0.f;
#pragma unroll
        for (int t = 0; t < 16; t++) v += red[tid][t];
        int n = n0 + tid;
        int i = n & 127;
        if (k <= i) g_sv[(size_t)n*TT + k] = v;
    }
}

// ---------------- Kernel 6: masked softmax combine ----------------
__global__ __launch_bounds__(256) void combine_kernel(
    const float* __restrict__ bo, float* __restrict__ out)
{
    int w = blockIdx.x * 8 + (threadIdx.x >> 5);
    int lane = threadIdx.x & 31;
    if (w >= NSEQ) return;
    int i = w & 127;
    float num = 0.f, den = 0.f;
    for (int k = lane; k <= i; k += 32) {
        float ev = __expf(g_pa[(size_t)w*TT + k]);
        num += ev * g_sv[(size_t)w*TT + k];
        den += ev;
    }
#pragma unroll
    for (int o = 16; o > 0; o >>= 1) {
        num += __shfl_xor_sync(0xffffffffu, num, o);
        den += __shfl_xor_sync(0xffffffffu, den, o);
    }
    if (lane == 0) out[w] = num / den + bo[0];
}

// ---------------- launch ----------------
extern "C" void kernel_launch(void* const* d_in, const int* in_sizes, int n_in,
                              void* d_out, int out_size)
{
    const float* x     = (const float*)d_in[0];
    const float* Wemb  = (const float*)d_in[1];
    const float* Wih_a = (const float*)d_in[2];
    const float* Whh_a = (const float*)d_in[3];
    const float* bih_a = (const float*)d_in[4];
    const float* bhh_a = (const float*)d_in[5];
    const float* Wa    = (const float*)d_in[6];
    const float* ba    = (const float*)d_in[7];
    const float* Wih_b = (const float*)d_in[8];
    const float* Whh_b = (const float*)d_in[9];
    const float* bih_b = (const float*)d_in[10];
    const float* bhh_b = (const float*)d_in[11];
    const float* Wb    = (const float*)d_in[12];
    const float* bb    = (const float*)d_in[13];
    const float* Wo    = (const float*)d_in[14];
    const float* bo    = (const float*)d_in[15];
    float* out = (float*)d_out;

    int dev = 0;
    cudaGetDevice(&dev);
    int sms = 148;
    cudaDeviceGetAttribute(&sms, cudaDevAttrMultiProcessorCount, dev);
    int RA = sms / 2;

    size_t smem_bytes = (size_t)SMEM_FLOATS * sizeof(float);
    cudaFuncSetAttribute(scan_kernel,
                         cudaFuncAttributeMaxDynamicSharedMemorySize,
                         (int)smem_bytes);

    dummy_kernel<<<1, 32>>>();
    emb_kernel<<<dim3(32, 4), 256>>>(x, Wemb, Wo);
    gx_kernel<<<dim3(32, 12), 256>>>(Wih_a, Wih_b, bih_a, bih_b);
    scan_kernel<<<sms, 384, smem_bytes>>>(Whh_a, Whh_b, bhh_a, bhh_b, RA, sms);
    alpha_kernel<<<(NSEQ*TT)/8, 256>>>(Wa, ba);
    beta_kernel<<<dim3(TT, NSEQ/64), 256>>>(Wb, bb);
    combine_kernel<<<NSEQ/8, 256>>>(bo, out);
}

// round 6
// speedup vs baseline: 1.7841x; 1.3160x over previous
#include <cuda_runtime.h>

#define BB 16
#define TT 128
#define DD 1024
#define EE 128
#define HHN 128
#define GG 384           // 3*H
#define NSEQ (BB*TT)     // 2048
#define NG8  256         // groups of 8 seqs (2 per time position i)

// scan smem layout (floats)
// [0, 32768): r,z weight pairs as ull: idx_ull = (t2*64 + p)*128 + u   (128KB)
#define OFF_SH2   32768                 // 8*132 hidden states
#define OFF_PART  (OFF_SH2 + 8*132)     // 2*8*3*128 partials
#define SMEM_FLOATS (OFF_PART + 6144)   // 39968 floats = 159872 B

// ---------------- scratch (device globals; no allocation) ----------------
__device__ float g_emb [NSEQ*EE];
__device__ float g_wemb[NSEQ*EE];       // Wo[e]*emb
__device__ float g_GXa [NSEQ*GG];
__device__ float g_GXb [NSEQ*GG];
__device__ float g_pa  [NSEQ*TT];       // pre_alpha[n][k]
__device__ float g_sv  [NSEQ*TT];       // s[n][k]
__device__ float g_hsa [(size_t)TT*NSEQ*HHN];   // h_a[k][n][h]
__device__ float g_hsb [(size_t)TT*NSEQ*HHN];   // h_b[k][n][h]
__device__ int   g_dummy;

typedef unsigned long long ull;

__device__ __forceinline__ void ffma2(ull &d, ull a, ull b) {
    asm("fma.rn.f32x2 %0, %1, %2, %0;" : "+l"(d) : "l"(a), "l"(b));
}
__device__ __forceinline__ ull lds64v(unsigned a) {
    ull v; asm volatile("ld.shared.b64 %0, [%1];" : "=l"(v) : "r"(a)); return v;
}
__device__ __forceinline__ void lds128v(unsigned a, ull &p0, ull &p1) {
    asm volatile("ld.shared.v2.b64 {%0,%1}, [%2];" : "=l"(p0), "=l"(p1) : "r"(a));
}
__device__ __forceinline__ float pairsum(ull v) {
    return __uint_as_float((unsigned)v) + __uint_as_float((unsigned)(v >> 32));
}
__device__ __forceinline__ ull dup2(float x) {
    ull v; asm("mov.b64 %0, {%1,%1};" : "=l"(v) : "f"(x)); return v;
}

// ---------------- dummy (keeps ncu capture slot on the scan) ----------------
__global__ void dummy_kernel() { if (threadIdx.x == 0) g_dummy = 1; }

// ---------------- Kernel 1: emb = x @ W_emb^T ; wemb = Wo .* emb ----------------
__global__ __launch_bounds__(256) void emb_kernel(
    const float* __restrict__ x, const float* __restrict__ Wemb,
    const float* __restrict__ Wo)
{
    __shared__ float sx[16][68];
    __shared__ float sw[16][36];
    int tid = threadIdx.x;
    int m0 = blockIdx.x * 64;
    int n0 = blockIdx.y * 32;
    int tx = tid & 15, ty = tid >> 4;
    int tm0 = tx * 4, tn0 = ty * 2;

    float acc[4][2];
#pragma unroll
    for (int q = 0; q < 4; q++) { acc[q][0] = 0.f; acc[q][1] = 0.f; }

    for (int kt = 0; kt < DD; kt += 16) {
        {
            int e = tid * 4; int m = e >> 4; int k = e & 15;
            float4 v = *(const float4*)(x + (size_t)(m0 + m) * DD + kt + k);
            sx[k][m] = v.x; sx[k+1][m] = v.y; sx[k+2][m] = v.z; sx[k+3][m] = v.w;
        }
        {
            int e = tid * 2; int n = e >> 4; int k = e & 15;
            float2 v = *(const float2*)(Wemb + (size_t)(n0 + n) * DD + kt + k);
            sw[k][n] = v.x; sw[k+1][n] = v.y;
        }
        __syncthreads();
#pragma unroll
        for (int k = 0; k < 16; k++) {
            float a0 = sx[k][tm0], a1 = sx[k][tm0+1], a2 = sx[k][tm0+2], a3 = sx[k][tm0+3];
            float b0 = sw[k][tn0], b1 = sw[k][tn0+1];
            acc[0][0] += a0*b0; acc[0][1] += a0*b1;
            acc[1][0] += a1*b0; acc[1][1] += a1*b1;
            acc[2][0] += a2*b0; acc[2][1] += a2*b1;
            acc[3][0] += a3*b0; acc[3][1] += a3*b1;
        }
        __syncthreads();
    }
#pragma unroll
    for (int q = 0; q < 4; q++)
#pragma unroll
        for (int r = 0; r < 2; r++) {
            int m = m0 + tm0 + q, n = n0 + tn0 + r;
            float v = acc[q][r];
            g_emb [m*EE + n] = v;
            g_wemb[m*EE + n] = v * Wo[n];
        }
}

// ---------------- Kernel 2: GX = emb @ Wih^T + bih (both GRUs) ----------------
__global__ __launch_bounds__(256) void gx_kernel(
    const float* __restrict__ Wih_a, const float* __restrict__ Wih_b,
    const float* __restrict__ bih_a, const float* __restrict__ bih_b)
{
    __shared__ float se [16][68];
    __shared__ float sw2[16][68];
    int tid = threadIdx.x;
    int m0 = blockIdx.x * 64;
    int n0 = blockIdx.y * 64;
    int tx = tid & 15, ty = tid >> 4;
    int tm0 = tx * 4, tn0 = ty * 4;

    const float* W; const float* bi; float* out; int nb;
    if (n0 < GG) { W = Wih_a; bi = bih_a; out = g_GXa; nb = n0; }
    else         { W = Wih_b; bi = bih_b; out = g_GXb; nb = n0 - GG; }

    float acc[4][4];
#pragma unroll
    for (int q = 0; q < 4; q++)
#pragma unroll
        for (int r = 0; r < 4; r++) acc[q][r] = 0.f;

    for (int kt = 0; kt < EE; kt += 16) {
        {
            int e = tid * 4; int m = e >> 4; int k = e & 15;
            float4 v = *(const float4*)(g_emb + (size_t)(m0 + m) * EE + kt + k);
            se[k][m] = v.x; se[k+1][m] = v.y; se[k+2][m] = v.z; se[k+3][m] = v.w;
        }
        {
            int e = tid * 4; int n = e >> 4; int k = e & 15;
            float4 v = *(const float4*)(W + (size_t)(nb + n) * EE + kt + k);
            sw2[k][n] = v.x; sw2[k+1][n] = v.y; sw2[k+2][n] = v.z; sw2[k+3][n] = v.w;
        }
        __syncthreads();
#pragma unroll
        for (int k = 0; k < 16; k++) {
            float a[4], b[4];
#pragma unroll
            for (int q = 0; q < 4; q++) a[q] = se[k][tm0+q];
#pragma unroll
            for (int r = 0; r < 4; r++) b[r] = sw2[k][tn0+r];
#pragma unroll
            for (int q = 0; q < 4; q++)
#pragma unroll
                for (int r = 0; r < 4; r++) acc[q][r] += a[q]*b[r];
        }
        __syncthreads();
    }
#pragma unroll
    for (int q = 0; q < 4; q++)
#pragma unroll
        for (int r = 0; r < 4; r++) {
            int m = m0 + tm0 + q, n = nb + tn0 + r;
            out[(size_t)m*GG + n] = acc[q][r] + bi[n];
        }
}

// ---------------- Kernel 3: persistent GRU scan ----------------
// 256 threads = (unit u 0..127) x (h-half). Thread computes r,z,n gate rows of
// its own unit over its h-half for 8 seqs, exchanges 24 partials, updates unit.
__global__ __launch_bounds__(256, 1) void scan_kernel(
    const float* __restrict__ Whh_a, const float* __restrict__ Whh_b,
    const float* __restrict__ bhh_a, const float* __restrict__ bhh_b,
    int RA, int Rtot)
{
    extern __shared__ float smem[];
    float* sh2  = smem + OFF_SH2;
    float* part = smem + OFF_PART;

    unsigned sbase;
    asm("{ .reg .u64 t; cvta.to.shared.u64 t, %1; cvt.u32.u64 %0, t; }"
        : "=r"(sbase) : "l"(smem));
    unsigned shA = sbase + OFF_SH2 * 4;    // h state, 528B per seq

    int tid = threadIdx.x;
    int u = tid & 127, half = tid >> 7;
    bool roleA = (blockIdx.x < RA);
    int rc = roleA ? blockIdx.x : blockIdx.x - RA;
    int R  = roleA ? RA : (Rtot - RA);

    const float* Whh = roleA ? Whh_a : Whh_b;
    const float* bhh = roleA ? bhh_a : bhh_b;
    const float* GX  = roleA ? g_GXa : g_GXb;
    float* HS        = roleA ? g_hsa : g_hsb;

    // stage r,z weight pairs to SMEM, layout [(t2*64+p)*128+u] (coalesced reads)
    {
        const ull* Wp = (const ull*)Whh;      // Wp[g*64 + p]
        ull* swrz = (ull*)smem;
        for (int idx = tid; idx < 16384; idx += 256) {
            int t2 = idx >> 13;
            int p  = (idx >> 7) & 63;
            int uu = idx & 127;
            swrz[idx] = Wp[(t2*128 + uu)*64 + p];
        }
    }
    // n-row half in registers (static indices, fully unrolled loops below)
    ull wn[32];
    {
        const ull* wnp = (const ull*)(Whh + (size_t)(256 + u) * HHN) + half*32;
#pragma unroll
        for (int q = 0; q < 32; q++) wn[q] = wnp[q];
    }
    float bhr = bhh[u], bhz = bhh[128 + u], bhn = bhh[256 + u];

    unsigned wbase_r = sbase + (unsigned)((half*32)*128 + u) * 8;
    unsigned wbase_z = wbase_r + 64*128*8;
    unsigned hbase0  = shA + (unsigned)half * 256;
    __syncthreads();

    for (int mIdx = 0;; mIdx++) {
        int g = mIdx*R + ((mIdx & 1) ? (R - 1 - rc) : rc);   // snake
        if (g >= NG8) break;

        int i  = 127 - (g >> 1);      // longest-first
        int b0 = (g & 1) * 8;

        __syncthreads();
        for (int idx = tid; idx < 8*132; idx += 256) sh2[idx] = 0.f;
        __syncthreads();

        for (int k = 0; k <= i; k++) {
            int j = i - k;
            // prefetch input-side gates for my 4 seqs (L2-resident)
            float gir[4], giz[4], gin[4];
#pragma unroll
            for (int ss = 0; ss < 4; ss++) {
                int s = half*4 + ss;
                int base = ((b0 + s)*TT + j)*GG;
                gir[ss] = __ldg(GX + base + u);
                giz[ss] = __ldg(GX + base + 128 + u);
                gin[ss] = __ldg(GX + base + 256 + u);
            }

            // ---- half-dots: 3 gates x 8 seqs over my h-half ----
            ull ar[8], az[8], an[8];
#pragma unroll
            for (int s = 0; s < 8; s++) { ar[s] = 0; az[s] = 0; an[s] = 0; }
#pragma unroll
            for (int blk = 0; blk < 16; blk++) {
                ull wr0 = lds64v(wbase_r + blk*2048);
                ull wr1 = lds64v(wbase_r + blk*2048 + 1024);
                ull wz0 = lds64v(wbase_z + blk*2048);
                ull wz1 = lds64v(wbase_z + blk*2048 + 1024);
                ull wn0 = wn[2*blk], wn1 = wn[2*blk+1];
#pragma unroll
                for (int s = 0; s < 8; s++) {
                    ull p0, p1;
                    lds128v(hbase0 + (unsigned)(s*528 + blk*16), p0, p1);
                    ffma2(ar[s], wr0, p0); ffma2(ar[s], wr1, p1);
                    ffma2(az[s], wz0, p0); ffma2(az[s], wz1, p1);
                    ffma2(an[s], wn0, p0); ffma2(an[s], wn1, p1);
                }
            }
            // write partials: part[((half*8+s)*3+t)*128+u]
#pragma unroll
            for (int s = 0; s < 8; s++) {
                part[((half*8 + s)*3 + 0)*128 + u] = pairsum(ar[s]);
                part[((half*8 + s)*3 + 1)*128 + u] = pairsum(az[s]);
                part[((half*8 + s)*3 + 2)*128 + u] = pairsum(an[s]);
            }
            __syncthreads();

            // ---- update my 4 seqs for unit u ----
#pragma unroll
            for (int ss = 0; ss < 4; ss++) {
                int s = half*4 + ss;
                float pr = part[(s*3 + 0)*128 + u] + part[((8 + s)*3 + 0)*128 + u];
                float pz = part[(s*3 + 1)*128 + u] + part[((8 + s)*3 + 1)*128 + u];
                float pn = part[(s*3 + 2)*128 + u] + part[((8 + s)*3 + 2)*128 + u];
                float rr = __fdividef(1.f, 1.f + __expf(-(pr + gir[ss] + bhr)));
                float zz = __fdividef(1.f, 1.f + __expf(-(pz + giz[ss] + bhz)));
                float nn = tanhf(gin[ss] + rr*(pn + bhn));
                float ho = sh2[s*132 + u];
                float h2 = (1.f - zz)*nn + zz*ho;
                sh2[s*132 + u] = h2;
                HS[((size_t)k*NSEQ + (b0 + s)*TT + i)*HHN + u] = h2;
            }
            __syncthreads();
        } // k
    } // groups
}

// ---------------- Kernel 4: pre_alpha = 0.5*Wa·h_a + ba ----------------
__global__ __launch_bounds__(256) void alpha_kernel(
    const float* __restrict__ Wa, const float* __restrict__ ba)
{
    int r = blockIdx.x * 8 + (threadIdx.x >> 5);   // (k,n) flat
    int lane = threadIdx.x & 31;
    int k = r >> 11, n = r & 2047, i = n & 127;
    if (k > i) return;
    const float4 hv = *(const float4*)(g_hsa + ((size_t)k*NSEQ + n)*HHN + lane*4);
    const float4 wv = *(const float4*)(Wa + lane*4);
    float p = 0.5f*(hv.x*wv.x + hv.y*wv.y + hv.z*wv.z + hv.w*wv.w);
#pragma unroll
    for (int o = 16; o > 0; o >>= 1)
        p += __shfl_xor_sync(0xffffffffu, p, o);
    if (lane == 0) g_pa[(size_t)n*TT + k] = p + ba[0];
}

// ---------------- Kernel 5: beta GEMM + wemb dot -> s[n][k] (f32x2) ----------------
__global__ __launch_bounds__(256) void beta_kernel(
    const float* __restrict__ Wb, const float* __restrict__ bb)
{
    int k  = blockIdx.x;          // 0..127
    int nb = blockIdx.y;          // 0..31
    int i0 = (nb & 1) * 64;
    if (i0 + 63 < k) return;
    int n0 = nb * 64;
    int b  = n0 >> 7;

    __shared__ float shh[16][68];
    __shared__ float sww[16][132];
    __shared__ float red[64][17];

    int tid = threadIdx.x;
    int tx = tid & 15, ty = tid >> 4;
    int r0 = tx * 4, e0 = ty * 8;

    const float* hb = g_hsb + ((size_t)k*NSEQ + n0)*HHN;

    ull acc2[4][4];
#pragma unroll
    for (int q = 0; q < 4; q++)
#pragma unroll
        for (int e = 0; e < 4; e++) acc2[q][e] = 0;

    for (int kt = 0; kt < HHN; kt += 16) {
        {
            int e = tid * 4; int rr = e >> 4; int h = e & 15;
            float4 v = *(const float4*)(hb + (size_t)rr*HHN + kt + h);
            shh[h][rr] = v.x; shh[h+1][rr] = v.y; shh[h+2][rr] = v.z; shh[h+3][rr] = v.w;
        }
        {
            int e2 = tid * 8; int ee = e2 >> 4; int h = e2 & 15;
            float4 v0 = *(const float4*)(Wb + (size_t)ee*HHN + kt + h);
            float4 v1 = *(const float4*)(Wb + (size_t)ee*HHN + kt + h + 4);
            sww[h  ][ee] = 0.5f*v0.x; sww[h+1][ee] = 0.5f*v0.y;
            sww[h+2][ee] = 0.5f*v0.z; sww[h+3][ee] = 0.5f*v0.w;
            sww[h+4][ee] = 0.5f*v1.x; sww[h+5][ee] = 0.5f*v1.y;
            sww[h+6][ee] = 0.5f*v1.z; sww[h+7][ee] = 0.5f*v1.w;
        }
        __syncthreads();
#pragma unroll
        for (int kk = 0; kk < 16; kk++) {
            ull av[4], bv[4];
#pragma unroll
            for (int q = 0; q < 4; q++) av[q] = dup2(shh[kk][r0+q]);
            const ull* bp = (const ull*)&sww[kk][e0];
#pragma unroll
            for (int e = 0; e < 4; e++) bv[e] = bp[e];
#pragma unroll
            for (int q = 0; q < 4; q++)
#pragma unroll
                for (int e = 0; e < 4; e++) ffma2(acc2[q][e], av[q], bv[e]);
        }
        __syncthreads();
    }

    float bbv[8];
#pragma unroll
    for (int e = 0; e < 8; e++) bbv[e] = bb[e0 + e];

#pragma unroll
    for (int q = 0; q < 4; q++) {
        int n = n0 + r0 + q;
        int i = n & 127;
        int j = i - k;
        const float* wm = g_wemb + ((size_t)b*TT + (j >= 0 ? j : 0))*EE + e0;
        float p = 0.f;
#pragma unroll
        for (int e = 0; e < 4; e++) {
            float lo = __uint_as_float((unsigned)acc2[q][e]);
            float hi = __uint_as_float((unsigned)(acc2[q][e] >> 32));
            p += tanhf(lo + bbv[2*e])   * wm[2*e];
            p += tanhf(hi + bbv[2*e+1]) * wm[2*e+1];
        }
        red[r0 + q][ty] = p;
    }
    __syncthreads();
    if (tid < 64) {
        float v = 0.f;
#pragma unroll
        for (int t = 0; t < 16; t++) v += red[tid][t];
        int n = n0 + tid;
        int i = n & 127;
        if (k <= i) g_sv[(size_t)n*TT + k] = v;
    }
}

// ---------------- Kernel 6: masked softmax combine ----------------
__global__ __launch_bounds__(256) void combine_kernel(
    const float* __restrict__ bo, float* __restrict__ out)
{
    int w = blockIdx.x * 8 + (threadIdx.x >> 5);
    int lane = threadIdx.x & 31;
    if (w >= NSEQ) return;
    int i = w & 127;
    float num = 0.f, den = 0.f;
    for (int k = lane; k <= i; k += 32) {
        float ev = __expf(g_pa[(size_t)w*TT + k]);
        num += ev * g_sv[(size_t)w*TT + k];
        den += ev;
    }
#pragma unroll
    for (int o = 16; o > 0; o >>= 1) {
        num += __shfl_xor_sync(0xffffffffu, num, o);
        den += __shfl_xor_sync(0xffffffffu, den, o);
    }
    if (lane == 0) out[w] = num / den + bo[0];
}

// ---------------- launch ----------------
extern "C" void kernel_launch(void* const* d_in, const int* in_sizes, int n_in,
                              void* d_out, int out_size)
{
    const float* x     = (const float*)d_in[0];
    const float* Wemb  = (const float*)d_in[1];
    const float* Wih_a = (const float*)d_in[2];
    const float* Whh_a = (const float*)d_in[3];
    const float* bih_a = (const float*)d_in[4];
    const float* bhh_a = (const float*)d_in[5];
    const float* Wa    = (const float*)d_in[6];
    const float* ba    = (const float*)d_in[7];
    const float* Wih_b = (const float*)d_in[8];
    const float* Whh_b = (const float*)d_in[9];
    const float* bih_b = (const float*)d_in[10];
    const float* bhh_b = (const float*)d_in[11];
    const float* Wb    = (const float*)d_in[12];
    const float* bb    = (const float*)d_in[13];
    const float* Wo    = (const float*)d_in[14];
    const float* bo    = (const float*)d_in[15];
    float* out = (float*)d_out;

    int dev = 0;
    cudaGetDevice(&dev);
    int sms = 148;
    cudaDeviceGetAttribute(&sms, cudaDevAttrMultiProcessorCount, dev);
    int RA = sms / 2;

    size_t smem_bytes = (size_t)SMEM_FLOATS * sizeof(float);
    cudaFuncSetAttribute(scan_kernel,
                         cudaFuncAttributeMaxDynamicSharedMemorySize,
                         (int)smem_bytes);

    dummy_kernel<<<1, 32>>>();
    emb_kernel<<<dim3(32, 4), 256>>>(x, Wemb, Wo);
    gx_kernel<<<dim3(32, 12), 256>>>(Wih_a, Wih_b, bih_a, bih_b);
    scan_kernel<<<sms, 256, smem_bytes>>>(Whh_a, Whh_b, bhh_a, bhh_b, RA, sms);
    alpha_kernel<<<(NSEQ*TT)/8, 256>>>(Wa, ba);
    beta_kernel<<<dim3(TT, NSEQ/64), 256>>>(Wb, bb);
    combine_kernel<<<NSEQ/8, 256>>>(bo, out);
}